// round 2
// baseline (speedup 1.0000x reference)
#include <cuda_runtime.h>
#include <cstdint>

#define NB 8
#define CC 64
#define HH 192
#define WW 192
#define HP 194
#define WP 194
#define NPIX (NB*HH*WW)      /* 294912 */
#define VOL  (NPIX*CC)       /* 18874368 */

// ---------------- scratch (static device globals; zero-initialized) ----------------
__device__ int8_t g_A1[NB*HP*WP*CC];     // quantized act 1, NHWC, zero-padded halo
__device__ int8_t g_A2[NB*HP*WP*CC];     // quantized act 2, NHWC, zero-padded halo
__device__ float  g_X1[VOL];             // conv1 output post-prelu, NHWC fp32
__device__ float  g_Y2[VOL];             // conv2 raw output, NHWC fp32
__device__ int8_t g_w1p[9*64*64];        // packed weights [tap][cout][cin] bytes
__device__ int8_t g_w2p[9*64*64];
__device__ float  g_S[2];                // combined conv scales (a_scale * w_scale)
__device__ double g_bn1s[CC], g_bn1q[CC], g_bn2s[CC], g_bn2q[CC];
__device__ float  g_c1s[CC], g_c1b[CC], g_c2s[CC], g_c2b[CC];

// ---------------- kernel 1: weight quantization + accumulator zeroing ----------------
__global__ void k_wquant(const float* __restrict__ w1, const float* __restrict__ w2,
                         const float* __restrict__ a1, const float* __restrict__ a2)
{
    int b = blockIdx.x, t = threadIdx.x;
    if (b == 2) {
        if (t < CC) { g_bn1s[t] = 0.0; g_bn1q[t] = 0.0; g_bn2s[t] = 0.0; g_bn2q[t] = 0.0; }
        return;
    }
    const float* w = b ? w2 : w1;
    int8_t* wp = b ? g_w2p : g_w1p;
    __shared__ float red[256];
    float m = 0.f;
    for (int i = t; i < 36864; i += 256) m = fmaxf(m, fabsf(w[i]));
    red[t] = m; __syncthreads();
    for (int s = 128; s; s >>= 1) { if (t < s) red[t] = fmaxf(red[t], red[t+s]); __syncthreads(); }
    float sw = red[0] / 127.0f;   // weight scale
    if (t == 0) g_S[b] = ((b ? a2[0] : a1[0]) / 127.0f) * sw;
    for (int i = t; i < 36864; i += 256) {
        float q = rintf(w[i] / sw);
        q = fminf(fmaxf(q, -127.f), 127.f);
        int o = i / 576, ci = (i / 9) % 64, tap = i % 9;
        wp[(tap*64 + o)*64 + ci] = (int8_t)q;     // [tap][cout][cin]
    }
}

// ---------------- kernel 2: quantize identity, NCHW fp32 -> NHWC int8 (padded) -------
__global__ void k_quant1(const float* __restrict__ x, const float* __restrict__ a1p)
{
    __shared__ uchar4 sb[32][17];
    int w0 = blockIdx.x*32, h = blockIdx.y, n = blockIdx.z;
    int tx = threadIdx.x, ty = threadIdx.y;         // 32 x 8
    float al = a1p[0], sc = al / 127.0f;
    #pragma unroll
    for (int k = 0; k < 2; k++) {
        int cg = ty + 8*k;                           // 0..15
        union { int8_t b[4]; uchar4 v; } u;
        #pragma unroll
        for (int j = 0; j < 4; j++) {
            int c = cg*4 + j;
            float xv = x[((n*CC + c)*HH + h)*WW + w0 + tx];
            xv = fminf(fmaxf(xv, -al), al);
            u.b[j] = (int8_t)(int)rintf(xv / sc);
        }
        sb[tx][cg] = u.v;
    }
    __syncthreads();
    int tid = ty*32 + tx;
    #pragma unroll
    for (int k = 0; k < 2; k++) {
        int uu = tid + 256*k;                        // 0..511
        int p = uu >> 4, cg = uu & 15;
        *reinterpret_cast<uchar4*>(&g_A1[((n*HP + h+1)*WP + (w0+p+1))*64 + cg*4]) = sb[p][cg];
    }
}

// ---------------- conv engine: int8 tensor-core implicit GEMM (IMMA m16n8k32) --------
// Block: 128 threads = 4 warps. Tile: 64 pixels (one row) x 64 couts, K = 9 taps x 64 cin.
// smem A: 3 rows x 66 pixels x 64B (XOR-swizzled at 16B granularity on (pix&6)).
// smem W: 9 taps x 64 couts x 64B (XOR-swizzled on (cout&6)).
template<bool FIRST>
__global__ void __launch_bounds__(128) k_conv(const float* __restrict__ pa_p)
{
    extern __shared__ int4 smem[];
    int4* sA = smem;                 // 792 int4  (12672 B)
    int4* sW = smem + 792;           // 2304 int4 (36864 B)
    const uint32_t* sAw = (const uint32_t*)sA;
    const uint32_t* sWw = (const uint32_t*)sW;

    const int8_t* A  = FIRST ? g_A1  : g_A2;
    const int4*   W4 = (const int4*)(FIRST ? g_w1p : g_w2p);
    float* Xout      = FIRST ? g_X1  : g_Y2;

    int tid = threadIdx.x;
    int lane = tid & 31, warp = tid >> 5;
    int w0 = blockIdx.x*64, h = blockIdx.y, n = blockIdx.z;

    const int4* A4 = (const int4*)A;
    for (int u = tid; u < 792; u += 128) {
        int dh = u / 264, rem = u % 264, pix = rem >> 2, c4 = rem & 3;
        sA[(dh*66 + pix)*4 + (c4 ^ ((pix & 6) >> 1))] =
            A4[((n*HP + h + dh)*WP + w0 + pix)*4 + c4];
    }
    for (int u = tid; u < 2304; u += 128) {
        int c4 = u & 3, co = (u >> 2) & 63, t = u >> 8;
        sW[(t*64 + co)*4 + (c4 ^ ((co & 6) >> 1))] = W4[u];
    }
    __syncthreads();

    int acc[8][4];
    #pragma unroll
    for (int o = 0; o < 8; o++)
        #pragma unroll
        for (int j = 0; j < 4; j++) acc[o][j] = 0;

    int g = lane >> 2, t4 = lane & 3;
    int pb = warp * 16;

    #pragma unroll 1
    for (int t = 0; t < 9; t++) {
        int dh = t / 3, dw = t % 3;
        #pragma unroll
        for (int c = 0; c < 2; c++) {
            int cin = 32*c + 4*t4;
            int p0 = pb + g + dw, p1 = p0 + 8;
            int off0 = (dh*66 + p0)*16 + (((cin) ^ ((p0 & 6) << 3)) >> 2);
            int off1 = (dh*66 + p1)*16 + (((cin) ^ ((p1 & 6) << 3)) >> 2);
            uint32_t a0 = sAw[off0];
            uint32_t a1 = sAw[off1];
            uint32_t a2 = sAw[off0 ^ 4];
            uint32_t a3 = sAw[off1 ^ 4];
            #pragma unroll
            for (int o = 0; o < 8; o++) {
                int co = o*8 + g;
                int boff = (t*64 + co)*16 + (((cin) ^ ((co & 6) << 3)) >> 2);
                uint32_t b0 = sWw[boff];
                uint32_t b1 = sWw[boff ^ 4];
                asm volatile(
                    "mma.sync.aligned.m16n8k32.row.col.s32.s8.s8.s32 "
                    "{%0,%1,%2,%3},{%4,%5,%6,%7},{%8,%9},{%0,%1,%2,%3};"
                    : "+r"(acc[o][0]), "+r"(acc[o][1]), "+r"(acc[o][2]), "+r"(acc[o][3])
                    : "r"(a0), "r"(a1), "r"(a2), "r"(a3), "r"(b0), "r"(b1));
            }
        }
    }

    float S  = g_S[FIRST ? 0 : 1];
    float pa = FIRST ? pa_p[0] : 0.f;
    int pixg = (n*HH + h)*WW + w0 + pb;
    int row0 = pixg + g, row1 = pixg + 8 + g;
    #pragma unroll
    for (int o = 0; o < 8; o++) {
        int col = o*8 + 2*t4;
        float y0 = S * (float)acc[o][0];
        float y1 = S * (float)acc[o][1];
        float y2 = S * (float)acc[o][2];
        float y3 = S * (float)acc[o][3];
        if (FIRST) {
            y0 = (y0 >= 0.f) ? y0 : pa*y0;
            y1 = (y1 >= 0.f) ? y1 : pa*y1;
            y2 = (y2 >= 0.f) ? y2 : pa*y2;
            y3 = (y3 >= 0.f) ? y3 : pa*y3;
        }
        *reinterpret_cast<float2*>(&Xout[row0*64 + col]) = make_float2(y0, y1);
        *reinterpret_cast<float2*>(&Xout[row1*64 + col]) = make_float2(y2, y3);
    }
}

// ---------------- BN per-channel sum/sumsq reduction over NHWC fp32 ------------------
template<bool FIRST>
__global__ void k_bnsum()
{
    const float4* X = (const float4*)(FIRST ? g_X1 : g_Y2);
    double* bs = FIRST ? g_bn1s : g_bn2s;
    double* bq = FIRST ? g_bn1q : g_bn2q;
    __shared__ float ss[64], sq[64];
    int tid = threadIdx.x;
    if (tid < 64) { ss[tid] = 0.f; sq[tid] = 0.f; }
    int cb = (tid*4) & 63;                           // constant channel base per thread
    float s0=0,s1=0,s2=0,s3=0,q0=0,q1=0,q2=0,q3=0;
    for (int i = blockIdx.x*256 + tid; i < VOL/4; i += gridDim.x*256) {
        float4 v = X[i];
        s0 += v.x; q0 += v.x*v.x;
        s1 += v.y; q1 += v.y*v.y;
        s2 += v.z; q2 += v.z*v.z;
        s3 += v.w; q3 += v.w*v.w;
    }
    __syncthreads();
    atomicAdd(&ss[cb+0], s0); atomicAdd(&sq[cb+0], q0);
    atomicAdd(&ss[cb+1], s1); atomicAdd(&sq[cb+1], q1);
    atomicAdd(&ss[cb+2], s2); atomicAdd(&sq[cb+2], q2);
    atomicAdd(&ss[cb+3], s3); atomicAdd(&sq[cb+3], q3);
    __syncthreads();
    if (tid < 64) {
        atomicAdd(&bs[tid], (double)ss[tid]);
        atomicAdd(&bq[tid], (double)sq[tid]);
    }
}

// ---------------- BN stats finalize -> per-channel scale/shift ----------------------
template<bool FIRST>
__global__ void k_stats(const float* __restrict__ gamma, const float* __restrict__ beta)
{
    int c = threadIdx.x;
    const double* bs = FIRST ? g_bn1s : g_bn2s;
    const double* bq = FIRST ? g_bn1q : g_bn2q;
    double invn = 1.0 / (double)NPIX;
    double mean = bs[c] * invn;
    double var  = bq[c] * invn - mean*mean;
    float scl = gamma[c] * rsqrtf((float)var + 1e-5f);
    if (FIRST) { g_c1s[c] = scl; g_c1b[c] = beta[c] - (float)mean * scl; }
    else       { g_c2s[c] = scl; g_c2b[c] = beta[c] - (float)mean * scl; }
}

// ---------------- fused BN1-apply + quant_act(alpha2) -> int8 NHWC padded ------------
__global__ void k_quant2(const float* __restrict__ a2p)
{
    int u = blockIdx.x*256 + threadIdx.x;           // over NPIX*16
    int p = u >> 4, cg = u & 15;
    float al = a2p[0], sc = al / 127.0f;
    float4 xv = *reinterpret_cast<const float4*>(&g_X1[p*64 + cg*4]);
    union { int8_t b[4]; uchar4 v; } r;
    const float* xf = (const float*)&xv;
    #pragma unroll
    for (int j = 0; j < 4; j++) {
        int c = cg*4 + j;
        float v = xf[j] * g_c1s[c] + g_c1b[c];
        v = fminf(fmaxf(v, -al), al);
        r.b[j] = (int8_t)(int)rintf(v / sc);
    }
    int n = p / (HH*WW), hw = p % (HH*WW), h = hw / WW, w = hw % WW;
    *reinterpret_cast<uchar4*>(&g_A2[((n*HP + h+1)*WP + (w+1))*64 + cg*4]) = r.v;
}

// ---------------- final: BN2-apply + NHWC->NCHW + residual + scalar tail -------------
__global__ void k_final(const float* __restrict__ idn, const float* __restrict__ shortcut,
                        float* __restrict__ out, const float* __restrict__ bits,
                        const float* __restrict__ f, const float* __restrict__ bout,
                        int out_size)
{
    __shared__ float sT[64][33];
    int w0 = blockIdx.x*32, h = blockIdx.y, n = blockIdx.z;
    int tx = threadIdx.x, ty = threadIdx.y;          // 32 x 8
    int tid = ty*32 + tx;
    int base = ((n*HH + h)*WW + w0)*64;
    #pragma unroll
    for (int k = 0; k < 8; k++) {
        int u = tid + 256*k;                         // 0..2047
        int c = u & 63, p = u >> 6;
        float y = g_Y2[base + u];
        sT[c][p] = y * g_c2s[c] + g_c2b[c];
    }
    __syncthreads();
    float sh = shortcut[0];
    #pragma unroll
    for (int k = 0; k < 8; k++) {
        int c = ty + 8*k;
        int o = ((n*CC + c)*HH + h)*WW + w0 + tx;
        out[o] = idn[o]*sh + sT[c][tx];
    }
    if (blockIdx.x == 0 && blockIdx.y == 0 && blockIdx.z == 0 && tid == 0 && out_size >= VOL + 3) {
        out[VOL]   = bits[0];
        out[VOL+1] = f[0];
        out[VOL+2] = bout[0];
    }
}

// ---------------- launch -------------------------------------------------------------
extern "C" void kernel_launch(void* const* d_in, const int* in_sizes, int n_in,
                              void* d_out, int out_size)
{
    (void)in_sizes; (void)n_in;
    const float* identity = (const float*)d_in[0];
    const float* bits     = (const float*)d_in[1];
    const float* f        = (const float*)d_in[2];
    const float* bits_out = (const float*)d_in[3];
    const float* w1       = (const float*)d_in[4];
    const float* w2       = (const float*)d_in[5];
    const float* alpha1   = (const float*)d_in[6];
    const float* alpha2   = (const float*)d_in[7];
    const float* gamma1   = (const float*)d_in[8];
    const float* beta1    = (const float*)d_in[9];
    const float* gamma2   = (const float*)d_in[10];
    const float* beta2    = (const float*)d_in[11];
    const float* prelu_a  = (const float*)d_in[12];
    const float* shortcut = (const float*)d_in[13];
    float* out = (float*)d_out;

    const int SMEM = (792 + 2304) * 16;  // 49536 B dynamic shared for conv
    cudaFuncSetAttribute(k_conv<true>,  cudaFuncAttributeMaxDynamicSharedMemorySize, SMEM);
    cudaFuncSetAttribute(k_conv<false>, cudaFuncAttributeMaxDynamicSharedMemorySize, SMEM);

    k_wquant<<<3, 256>>>(w1, w2, alpha1, alpha2);
    k_quant1<<<dim3(6,192,8), dim3(32,8)>>>(identity, alpha1);
    k_conv<true><<<dim3(3,192,8), 128, SMEM>>>(prelu_a);
    k_bnsum<true><<<1184, 256>>>();
    k_stats<true><<<1, 64>>>(gamma1, beta1);
    k_quant2<<<(NPIX*16)/256, 256>>>(alpha2);
    k_conv<false><<<dim3(3,192,8), 128, SMEM>>>(prelu_a);
    k_bnsum<false><<<1184, 256>>>();
    k_stats<false><<<1, 64>>>(gamma2, beta2);
    k_final<<<dim3(6,192,8), dim3(32,8)>>>(identity, shortcut, out, bits, f, bits_out, out_size);
}

// round 4
// speedup vs baseline: 1.1279x; 1.1279x over previous
#include <cuda_runtime.h>
#include <cstdint>

#define NB 8
#define CC 64
#define HH 192
#define WW 192
#define HP 194
#define WP 194
#define NPIX (NB*HH*WW)      /* 294912 */
#define VOL  (NPIX*CC)       /* 18874368 */
#define HW   (HH*WW)         /* 36864 */

// ---------------- scratch (static device globals; zero-initialized) ----------------
__device__ int8_t g_A1[NB*HP*WP*CC];     // quantized act 1, NHWC, zero-padded halo
__device__ int8_t g_A2[NB*HP*WP*CC];     // quantized act 2, NHWC, zero-padded halo
__device__ float  g_X1[VOL];             // conv1 output post-prelu, NHWC fp32
__device__ float  g_Y2[VOL];             // conv2 raw output, NCHW fp32
__device__ int8_t g_w1p[9*64*64];        // packed weights [tap][cout][cin] bytes
__device__ int8_t g_w2p[9*64*64];
__device__ float  g_S[2];                // combined conv scales (a_scale * w_scale)
__device__ double g_bn1s[CC], g_bn1q[CC], g_bn2s[CC], g_bn2q[CC];
__device__ float  g_c1s[CC], g_c1b[CC], g_c2s[CC], g_c2b[CC];

// ---------------- kernel 1: weight quantization + accumulator zeroing ----------------
__global__ void k_wquant(const float* __restrict__ w1, const float* __restrict__ w2,
                         const float* __restrict__ a1, const float* __restrict__ a2)
{
    int b = blockIdx.x, t = threadIdx.x;
    if (b == 2) {
        if (t < CC) { g_bn1s[t] = 0.0; g_bn1q[t] = 0.0; g_bn2s[t] = 0.0; g_bn2q[t] = 0.0; }
        return;
    }
    const float* w = b ? w2 : w1;
    int8_t* wp = b ? g_w2p : g_w1p;
    __shared__ float red[256];
    float m = 0.f;
    for (int i = t; i < 36864; i += 256) m = fmaxf(m, fabsf(w[i]));
    red[t] = m; __syncthreads();
    for (int s = 128; s; s >>= 1) { if (t < s) red[t] = fmaxf(red[t], red[t+s]); __syncthreads(); }
    float sw = red[0] / 127.0f;   // weight scale
    if (t == 0) g_S[b] = ((b ? a2[0] : a1[0]) / 127.0f) * sw;
    for (int i = t; i < 36864; i += 256) {
        float q = rintf(w[i] / sw);
        q = fminf(fmaxf(q, -127.f), 127.f);
        int o = i / 576, ci = (i / 9) % 64, tap = i % 9;
        wp[(tap*64 + o)*64 + ci] = (int8_t)q;     // [tap][cout][cin]
    }
}

// ---------------- kernel 2: quantize identity, NCHW fp32 -> NHWC int8 (padded) -------
__global__ void k_quant1(const float* __restrict__ x, const float* __restrict__ a1p)
{
    __shared__ uchar4 sb[32][17];
    int w0 = blockIdx.x*32, h = blockIdx.y, n = blockIdx.z;
    int tx = threadIdx.x, ty = threadIdx.y;         // 32 x 8
    float al = a1p[0], sc = al / 127.0f;
    #pragma unroll
    for (int k = 0; k < 2; k++) {
        int cg = ty + 8*k;                           // 0..15
        union { int8_t b[4]; uchar4 v; } u;
        #pragma unroll
        for (int j = 0; j < 4; j++) {
            int c = cg*4 + j;
            float xv = x[((n*CC + c)*HH + h)*WW + w0 + tx];
            xv = fminf(fmaxf(xv, -al), al);
            u.b[j] = (int8_t)(int)rintf(xv / sc);
        }
        sb[tx][cg] = u.v;
    }
    __syncthreads();
    int tid = ty*32 + tx;
    #pragma unroll
    for (int k = 0; k < 2; k++) {
        int uu = tid + 256*k;                        // 0..511
        int p = uu >> 4, cg = uu & 15;
        *reinterpret_cast<uchar4*>(&g_A1[((n*HP + h+1)*WP + (w0+p+1))*64 + cg*4]) = sb[p][cg];
    }
}

// ---------------- conv engine: int8 tensor-core implicit GEMM (IMMA m16n8k32) --------
// Block: 256 threads = 8 warps. Tile: 128 pixels (2 rows x 64 wide) x 64 couts.
// Fused epilogue: fp32 store (NHWC for conv1, NCHW for conv2) + per-channel
// sum/sumsq (fp32) -> global double atomics.
template<bool FIRST>
__global__ void __launch_bounds__(256) k_conv(const float* __restrict__ pa_p)
{
    extern __shared__ int4 smem[];
    int4* sA = smem;                 // 4 rows x 66 pix x 4 = 1056 int4
    int4* sW = smem + 1056;          // 2304 int4
    __shared__ float ss[64], sq[64];
    const uint32_t* sAw = (const uint32_t*)sA;
    const uint32_t* sWw = (const uint32_t*)sW;

    const int8_t* A  = FIRST ? g_A1  : g_A2;
    const int4*   W4 = (const int4*)(FIRST ? g_w1p : g_w2p);
    float* Xout      = FIRST ? g_X1  : g_Y2;
    double* bs       = FIRST ? g_bn1s : g_bn2s;
    double* bq       = FIRST ? g_bn1q : g_bn2q;

    int tid = threadIdx.x;
    int lane = tid & 31, warp = tid >> 5;
    int w0 = blockIdx.x*64, H0 = blockIdx.y*2, n = blockIdx.z;

    if (tid < 64) { ss[tid] = 0.f; sq[tid] = 0.f; }

    const int4* A4 = (const int4*)A;
    for (int u = tid; u < 1056; u += 256) {
        int r = u / 264, rem = u % 264, pix = rem >> 2, c4 = rem & 3;
        sA[(r*66 + pix)*4 + (c4 ^ ((pix & 6) >> 1))] =
            A4[((n*HP + H0 + r)*WP + w0 + pix)*4 + c4];
    }
    for (int u = tid; u < 2304; u += 256) {
        int c4 = u & 3, co = (u >> 2) & 63, t = u >> 8;
        sW[(t*64 + co)*4 + (c4 ^ ((co & 6) >> 1))] = W4[u];
    }
    __syncthreads();

    int g = lane >> 2, t4 = lane & 3;
    int pg = warp >> 1, ch = warp & 1;
    int lrow = pg >> 1, colb = (pg & 1) * 32;

    int acc[2][4][4];
    #pragma unroll
    for (int mg = 0; mg < 2; mg++)
        #pragma unroll
        for (int o = 0; o < 4; o++)
            #pragma unroll
            for (int j = 0; j < 4; j++) acc[mg][o][j] = 0;

    #pragma unroll 1
    for (int t = 0; t < 9; t++) {
        int dh = t / 3, dw = t % 3;
        int rs = lrow + dh;
        uint32_t af[2][2][4];
        #pragma unroll
        for (int c = 0; c < 2; c++) {
            int cin = 32*c + 4*t4;
            #pragma unroll
            for (int mg = 0; mg < 2; mg++) {
                int p0 = colb + mg*16 + g + dw;
                int off = (rs*66 + p0)*16 + ((cin ^ ((p0 & 6) << 3)) >> 2);
                af[c][mg][0] = sAw[off];
                af[c][mg][1] = sAw[off + 128];       // p0+8 keeps (p&6) bits
                af[c][mg][2] = sAw[off ^ 4];
                af[c][mg][3] = sAw[(off + 128) ^ 4];
            }
        }
        #pragma unroll
        for (int o = 0; o < 4; o++) {
            int co = ch*32 + o*8 + g;
            #pragma unroll
            for (int c = 0; c < 2; c++) {
                int cin = 32*c + 4*t4;
                int boff = (t*64 + co)*16 + ((cin ^ ((co & 6) << 3)) >> 2);
                uint32_t b0 = sWw[boff];
                uint32_t b1 = sWw[boff ^ 4];
                #pragma unroll
                for (int mg = 0; mg < 2; mg++) {
                    asm volatile(
                        "mma.sync.aligned.m16n8k32.row.col.s32.s8.s8.s32 "
                        "{%0,%1,%2,%3},{%4,%5,%6,%7},{%8,%9},{%0,%1,%2,%3};"
                        : "+r"(acc[mg][o][0]), "+r"(acc[mg][o][1]),
                          "+r"(acc[mg][o][2]), "+r"(acc[mg][o][3])
                        : "r"(af[c][mg][0]), "r"(af[c][mg][1]),
                          "r"(af[c][mg][2]), "r"(af[c][mg][3]),
                          "r"(b0), "r"(b1));
                }
            }
        }
    }

    float S  = g_S[FIRST ? 0 : 1];
    float pa = FIRST ? pa_p[0] : 0.f;
    float sj[4][2], qj[4][2];
    #pragma unroll
    for (int o = 0; o < 4; o++) { sj[o][0]=sj[o][1]=qj[o][0]=qj[o][1]=0.f; }

    #pragma unroll
    for (int mg = 0; mg < 2; mg++) {
        int pixl = (H0 + lrow)*WW + w0 + colb + mg*16;   // pixel index within image
        #pragma unroll
        for (int o = 0; o < 4; o++) {
            int col = ch*32 + o*8 + 2*t4;
            float y0 = S * (float)acc[mg][o][0];
            float y1 = S * (float)acc[mg][o][1];
            float y2 = S * (float)acc[mg][o][2];
            float y3 = S * (float)acc[mg][o][3];
            if (FIRST) {
                y0 = (y0 >= 0.f) ? y0 : pa*y0;
                y1 = (y1 >= 0.f) ? y1 : pa*y1;
                y2 = (y2 >= 0.f) ? y2 : pa*y2;
                y3 = (y3 >= 0.f) ? y3 : pa*y3;
                int row0 = n*HW + pixl + g, row1 = row0 + 8;
                *reinterpret_cast<float2*>(&Xout[row0*64 + col]) = make_float2(y0, y1);
                *reinterpret_cast<float2*>(&Xout[row1*64 + col]) = make_float2(y2, y3);
            } else {
                // NCHW direct: out[((n*64+c)*HW) + pix]
                int b0 = (n*64 + col)*HW + pixl;
                int b1 = (n*64 + col + 1)*HW + pixl;
                Xout[b0 + g]     = y0;
                Xout[b1 + g]     = y1;
                Xout[b0 + 8 + g] = y2;
                Xout[b1 + 8 + g] = y3;
            }
            sj[o][0] += y0 + y2;  qj[o][0] += y0*y0 + y2*y2;
            sj[o][1] += y1 + y3;  qj[o][1] += y1*y1 + y3*y3;
        }
    }
    // reduce over g (lane bits 2..4), then smem atomics from g==0 lanes
    #pragma unroll
    for (int o = 0; o < 4; o++) {
        #pragma unroll
        for (int j = 0; j < 2; j++) {
            float s = sj[o][j], q = qj[o][j];
            #pragma unroll
            for (int off = 4; off < 32; off <<= 1) {
                s += __shfl_xor_sync(0xffffffffu, s, off);
                q += __shfl_xor_sync(0xffffffffu, q, off);
            }
            if (g == 0) {
                int chan = ch*32 + o*8 + t4*2 + j;
                atomicAdd(&ss[chan], s);
                atomicAdd(&sq[chan], q);
            }
        }
    }
    __syncthreads();
    if (tid < 64) {
        atomicAdd(&bs[tid], (double)ss[tid]);
        atomicAdd(&bq[tid], (double)sq[tid]);
    }
}

// ---------------- BN stats finalize -> per-channel scale/shift ----------------------
template<bool FIRST>
__global__ void k_stats(const float* __restrict__ gamma, const float* __restrict__ beta)
{
    int c = threadIdx.x;
    const double* bs = FIRST ? g_bn1s : g_bn2s;
    const double* bq = FIRST ? g_bn1q : g_bn2q;
    double invn = 1.0 / (double)NPIX;
    double mean = bs[c] * invn;
    double var  = bq[c] * invn - mean*mean;
    float scl = gamma[c] * rsqrtf((float)var + 1e-5f);
    if (FIRST) { g_c1s[c] = scl; g_c1b[c] = beta[c] - (float)mean * scl; }
    else       { g_c2s[c] = scl; g_c2b[c] = beta[c] - (float)mean * scl; }
}

// ---------------- fused BN1-apply + quant_act(alpha2) -> int8 NHWC padded ------------
__global__ void k_quant2(const float* __restrict__ a2p)
{
    int u = blockIdx.x*256 + threadIdx.x;           // over NPIX*16
    int p = u >> 4, cg = u & 15;
    float al = a2p[0], sc = al / 127.0f;
    float4 xv = *reinterpret_cast<const float4*>(&g_X1[p*64 + cg*4]);
    union { int8_t b[4]; uchar4 v; } r;
    const float* xf = (const float*)&xv;
    #pragma unroll
    for (int j = 0; j < 4; j++) {
        int c = cg*4 + j;
        float v = xf[j] * g_c1s[c] + g_c1b[c];
        v = fminf(fmaxf(v, -al), al);
        r.b[j] = (int8_t)(int)rintf(v / sc);
    }
    int n = p / HW, hw = p % HW, h = hw / WW, w = hw % WW;
    *reinterpret_cast<uchar4*>(&g_A2[((n*HP + h+1)*WP + (w+1))*64 + cg*4]) = r.v;
}

// ---------------- final: pure elementwise NCHW (Y2 already NCHW) ---------------------
__global__ void k_final(const float* __restrict__ idn, const float* __restrict__ shortcut,
                        float* __restrict__ out, const float* __restrict__ bits,
                        const float* __restrict__ f, const float* __restrict__ bout,
                        int out_size)
{
    int c = blockIdx.y, n = blockIdx.z;
    int base4 = ((n*CC + c)*HW >> 2) + blockIdx.x*256 + threadIdx.x;  // float4 index
    float scl = g_c2s[c], sft = g_c2b[c], sh = shortcut[0];
    float4 y = reinterpret_cast<const float4*>(g_Y2)[base4];
    float4 v = reinterpret_cast<const float4*>(idn)[base4];
    float4 r;
    r.x = v.x*sh + y.x*scl + sft;
    r.y = v.y*sh + y.y*scl + sft;
    r.z = v.z*sh + y.z*scl + sft;
    r.w = v.w*sh + y.w*scl + sft;
    reinterpret_cast<float4*>(out)[base4] = r;
    if (blockIdx.x == 0 && blockIdx.y == 0 && blockIdx.z == 0 && threadIdx.x == 0
        && out_size >= VOL + 3) {
        out[VOL]   = bits[0];
        out[VOL+1] = f[0];
        out[VOL+2] = bout[0];
    }
}

// ---------------- launch -------------------------------------------------------------
extern "C" void kernel_launch(void* const* d_in, const int* in_sizes, int n_in,
                              void* d_out, int out_size)
{
    (void)in_sizes; (void)n_in;
    const float* identity = (const float*)d_in[0];
    const float* bits     = (const float*)d_in[1];
    const float* f        = (const float*)d_in[2];
    const float* bits_out = (const float*)d_in[3];
    const float* w1       = (const float*)d_in[4];
    const float* w2       = (const float*)d_in[5];
    const float* alpha1   = (const float*)d_in[6];
    const float* alpha2   = (const float*)d_in[7];
    const float* gamma1   = (const float*)d_in[8];
    const float* beta1    = (const float*)d_in[9];
    const float* gamma2   = (const float*)d_in[10];
    const float* beta2    = (const float*)d_in[11];
    const float* prelu_a  = (const float*)d_in[12];
    const float* shortcut = (const float*)d_in[13];
    float* out = (float*)d_out;

    const int SMEM = (1056 + 2304) * 16;  // 53760 B dynamic shared for conv
    cudaFuncSetAttribute(k_conv<true>,  cudaFuncAttributeMaxDynamicSharedMemorySize, SMEM);
    cudaFuncSetAttribute(k_conv<false>, cudaFuncAttributeMaxDynamicSharedMemorySize, SMEM);

    k_wquant<<<3, 256>>>(w1, w2, alpha1, alpha2);
    k_quant1<<<dim3(6,192,8), dim3(32,8)>>>(identity, alpha1);
    k_conv<true><<<dim3(3,96,8), 256, SMEM>>>(prelu_a);
    k_stats<true><<<1, 64>>>(gamma1, beta1);
    k_quant2<<<(NPIX*16)/256, 256>>>(alpha2);
    k_conv<false><<<dim3(3,96,8), 256, SMEM>>>(prelu_a);
    k_stats<false><<<1, 64>>>(gamma2, beta2);
    k_final<<<dim3(HW/4/256, CC, NB), 256>>>(identity, shortcut, out, bits, f, bits_out, out_size);
}

// round 5
// speedup vs baseline: 1.1486x; 1.0183x over previous
#include <cuda_runtime.h>
#include <cuda_fp16.h>
#include <cstdint>

#define NB 8
#define CC 64
#define HH 192
#define WW 192
#define HP 194
#define WP 194
#define NPIX (NB*HH*WW)      /* 294912 */
#define VOL  (NPIX*CC)       /* 18874368 */
#define HW   (HH*WW)         /* 36864 */

// ---------------- scratch (static device globals; zero-initialized) ----------------
__device__ int8_t g_A1[NB*HP*WP*CC];     // quantized act 1, NHWC, zero-padded halo
__device__ int8_t g_A2[NB*HP*WP*CC];     // quantized act 2, NHWC, zero-padded halo
__device__ float  g_X1[VOL];             // conv1 output post-prelu, NHWC fp32 (feeds round())
__device__ __half g_Y2h[VOL];            // conv2 raw output, NCHW fp16 (affine-only downstream)
__device__ int8_t g_w1p[9*64*64];        // packed weights [tap][cout][cin] bytes
__device__ int8_t g_w2p[9*64*64];
__device__ float  g_S[2];                // combined conv scales (a_scale * w_scale)
__device__ double g_bn1s[CC], g_bn1q[CC], g_bn2s[CC], g_bn2q[CC];
__device__ float  g_c1s[CC], g_c1b[CC], g_c2s[CC], g_c2b[CC];

// ---------------- kernel 1: weight quantization + accumulator zeroing ----------------
__global__ void k_wquant(const float* __restrict__ w1, const float* __restrict__ w2,
                         const float* __restrict__ a1, const float* __restrict__ a2)
{
    int b = blockIdx.x, t = threadIdx.x;
    if (b == 2) {
        if (t < CC) { g_bn1s[t] = 0.0; g_bn1q[t] = 0.0; g_bn2s[t] = 0.0; g_bn2q[t] = 0.0; }
        return;
    }
    const float* w = b ? w2 : w1;
    int8_t* wp = b ? g_w2p : g_w1p;
    __shared__ float red[256];
    float m = 0.f;
    for (int i = t; i < 36864; i += 256) m = fmaxf(m, fabsf(w[i]));
    red[t] = m; __syncthreads();
    for (int s = 128; s; s >>= 1) { if (t < s) red[t] = fmaxf(red[t], red[t+s]); __syncthreads(); }
    float sw = red[0] / 127.0f;   // weight scale
    if (t == 0) g_S[b] = ((b ? a2[0] : a1[0]) / 127.0f) * sw;
    for (int i = t; i < 36864; i += 256) {
        float q = rintf(w[i] / sw);
        q = fminf(fmaxf(q, -127.f), 127.f);
        int o = i / 576, ci = (i / 9) % 64, tap = i % 9;
        wp[(tap*64 + o)*64 + ci] = (int8_t)q;     // [tap][cout][cin]
    }
}

// ---------------- kernel 2: quantize identity, NCHW fp32 -> NHWC int8 (padded) -------
__global__ void k_quant1(const float* __restrict__ x, const float* __restrict__ a1p)
{
    __shared__ uchar4 sb[32][17];
    int w0 = blockIdx.x*32, h = blockIdx.y, n = blockIdx.z;
    int tx = threadIdx.x, ty = threadIdx.y;         // 32 x 8
    float al = a1p[0], sc = al / 127.0f;
    #pragma unroll
    for (int k = 0; k < 2; k++) {
        int cg = ty + 8*k;                           // 0..15
        union { int8_t b[4]; uchar4 v; } u;
        #pragma unroll
        for (int j = 0; j < 4; j++) {
            int c = cg*4 + j;
            float xv = x[((n*CC + c)*HH + h)*WW + w0 + tx];
            xv = fminf(fmaxf(xv, -al), al);
            u.b[j] = (int8_t)(int)rintf(xv / sc);
        }
        sb[tx][cg] = u.v;
    }
    __syncthreads();
    int tid = ty*32 + tx;
    #pragma unroll
    for (int k = 0; k < 2; k++) {
        int uu = tid + 256*k;                        // 0..511
        int p = uu >> 4, cg = uu & 15;
        *reinterpret_cast<uchar4*>(&g_A1[((n*HP + h+1)*WP + (w0+p+1))*64 + cg*4]) = sb[p][cg];
    }
}

// ---------------- conv engine: int8 tensor-core implicit GEMM (IMMA m16n8k32) --------
// Block: 512 threads = 16 warps. Tile: 256 pixels (4 rows x 64 wide) x 64 couts.
// Warp w: pg=w>>1 (32-pixel group: row pg>>1, col-half pg&1), cout half ch=w&1.
// Fused epilogue: store (NHWC fp32 for conv1, NCHW fp16 for conv2) + per-channel
// sum/sumsq (fp32) -> global double atomics.
template<bool FIRST>
__global__ void __launch_bounds__(512) k_conv(const float* __restrict__ pa_p)
{
    extern __shared__ int4 smem[];
    int4* sA = smem;                 // 6 rows x 66 pix x 4 = 1584 int4
    int4* sW = smem + 1584;          // 2304 int4
    __shared__ float ss[64], sq[64];
    const uint32_t* sAw = (const uint32_t*)sA;
    const uint32_t* sWw = (const uint32_t*)sW;

    const int8_t* A  = FIRST ? g_A1  : g_A2;
    const int4*   W4 = (const int4*)(FIRST ? g_w1p : g_w2p);
    double* bs       = FIRST ? g_bn1s : g_bn2s;
    double* bq       = FIRST ? g_bn1q : g_bn2q;

    int tid = threadIdx.x;
    int lane = tid & 31, warp = tid >> 5;
    int w0 = blockIdx.x*64, H0 = blockIdx.y*4, n = blockIdx.z;

    if (tid < 64) { ss[tid] = 0.f; sq[tid] = 0.f; }

    const int4* A4 = (const int4*)A;
    for (int u = tid; u < 1584; u += 512) {
        int r = u / 264, rem = u % 264, pix = rem >> 2, c4 = rem & 3;
        sA[(r*66 + pix)*4 + (c4 ^ ((pix & 6) >> 1))] =
            A4[((n*HP + H0 + r)*WP + w0 + pix)*4 + c4];
    }
    for (int u = tid; u < 2304; u += 512) {
        int c4 = u & 3, co = (u >> 2) & 63, t = u >> 8;
        sW[(t*64 + co)*4 + (c4 ^ ((co & 6) >> 1))] = W4[u];
    }
    __syncthreads();

    int g = lane >> 2, t4 = lane & 3;
    int pg = warp >> 1, ch = warp & 1;
    int lrow = pg >> 1, colb = (pg & 1) * 32;

    int acc[2][4][4];
    #pragma unroll
    for (int mg = 0; mg < 2; mg++)
        #pragma unroll
        for (int o = 0; o < 4; o++)
            #pragma unroll
            for (int j = 0; j < 4; j++) acc[mg][o][j] = 0;

    #pragma unroll 1
    for (int t = 0; t < 9; t++) {
        int dh = t / 3, dw = t % 3;
        int rs = lrow + dh;
        uint32_t af[2][2][4];
        #pragma unroll
        for (int c = 0; c < 2; c++) {
            int cin = 32*c + 4*t4;
            #pragma unroll
            for (int mg = 0; mg < 2; mg++) {
                int p0 = colb + mg*16 + g + dw;
                int off = (rs*66 + p0)*16 + ((cin ^ ((p0 & 6) << 3)) >> 2);
                af[c][mg][0] = sAw[off];
                af[c][mg][1] = sAw[off + 128];       // p0+8 keeps (p&6) bits
                af[c][mg][2] = sAw[off ^ 4];
                af[c][mg][3] = sAw[(off + 128) ^ 4];
            }
        }
        #pragma unroll
        for (int o = 0; o < 4; o++) {
            int co = ch*32 + o*8 + g;
            #pragma unroll
            for (int c = 0; c < 2; c++) {
                int cin = 32*c + 4*t4;
                int boff = (t*64 + co)*16 + ((cin ^ ((co & 6) << 3)) >> 2);
                uint32_t b0 = sWw[boff];
                uint32_t b1 = sWw[boff ^ 4];
                #pragma unroll
                for (int mg = 0; mg < 2; mg++) {
                    asm volatile(
                        "mma.sync.aligned.m16n8k32.row.col.s32.s8.s8.s32 "
                        "{%0,%1,%2,%3},{%4,%5,%6,%7},{%8,%9},{%0,%1,%2,%3};"
                        : "+r"(acc[mg][o][0]), "+r"(acc[mg][o][1]),
                          "+r"(acc[mg][o][2]), "+r"(acc[mg][o][3])
                        : "r"(af[c][mg][0]), "r"(af[c][mg][1]),
                          "r"(af[c][mg][2]), "r"(af[c][mg][3]),
                          "r"(b0), "r"(b1));
                }
            }
        }
    }

    float S  = g_S[FIRST ? 0 : 1];
    float pa = FIRST ? pa_p[0] : 0.f;
    float sj[4][2], qj[4][2];
    #pragma unroll
    for (int o = 0; o < 4; o++) { sj[o][0]=sj[o][1]=qj[o][0]=qj[o][1]=0.f; }

    #pragma unroll
    for (int mg = 0; mg < 2; mg++) {
        int pixl = (H0 + lrow)*WW + w0 + colb + mg*16;   // pixel index within image
        #pragma unroll
        for (int o = 0; o < 4; o++) {
            int col = ch*32 + o*8 + 2*t4;
            float y0 = S * (float)acc[mg][o][0];
            float y1 = S * (float)acc[mg][o][1];
            float y2 = S * (float)acc[mg][o][2];
            float y3 = S * (float)acc[mg][o][3];
            if (FIRST) {
                y0 = (y0 >= 0.f) ? y0 : pa*y0;
                y1 = (y1 >= 0.f) ? y1 : pa*y1;
                y2 = (y2 >= 0.f) ? y2 : pa*y2;
                y3 = (y3 >= 0.f) ? y3 : pa*y3;
                int row0 = n*HW + pixl + g, row1 = row0 + 8;
                *reinterpret_cast<float2*>(&g_X1[row0*64 + col]) = make_float2(y0, y1);
                *reinterpret_cast<float2*>(&g_X1[row1*64 + col]) = make_float2(y2, y3);
            } else {
                // NCHW fp16 direct: y0/y2 fill a contiguous 32B run per channel
                int b0 = (n*64 + col)*HW + pixl;
                int b1 = b0 + HW;
                g_Y2h[b0 + g]     = __float2half_rn(y0);
                g_Y2h[b1 + g]     = __float2half_rn(y1);
                g_Y2h[b0 + 8 + g] = __float2half_rn(y2);
                g_Y2h[b1 + 8 + g] = __float2half_rn(y3);
            }
            sj[o][0] += y0 + y2;  qj[o][0] += y0*y0 + y2*y2;
            sj[o][1] += y1 + y3;  qj[o][1] += y1*y1 + y3*y3;
        }
    }
    // reduce over g (lane bits 2..4), then smem atomics from g==0 lanes
    #pragma unroll
    for (int o = 0; o < 4; o++) {
        #pragma unroll
        for (int j = 0; j < 2; j++) {
            float s = sj[o][j], q = qj[o][j];
            #pragma unroll
            for (int off = 4; off < 32; off <<= 1) {
                s += __shfl_xor_sync(0xffffffffu, s, off);
                q += __shfl_xor_sync(0xffffffffu, q, off);
            }
            if (g == 0) {
                int chan = ch*32 + o*8 + t4*2 + j;
                atomicAdd(&ss[chan], s);
                atomicAdd(&sq[chan], q);
            }
        }
    }
    __syncthreads();
    if (tid < 64) {
        atomicAdd(&bs[tid], (double)ss[tid]);
        atomicAdd(&bq[tid], (double)sq[tid]);
    }
}

// ---------------- BN stats finalize -> per-channel scale/shift ----------------------
template<bool FIRST>
__global__ void k_stats(const float* __restrict__ gamma, const float* __restrict__ beta)
{
    int c = threadIdx.x;
    const double* bs = FIRST ? g_bn1s : g_bn2s;
    const double* bq = FIRST ? g_bn1q : g_bn2q;
    double invn = 1.0 / (double)NPIX;
    double mean = bs[c] * invn;
    double var  = bq[c] * invn - mean*mean;
    float scl = gamma[c] * rsqrtf((float)var + 1e-5f);
    if (FIRST) { g_c1s[c] = scl; g_c1b[c] = beta[c] - (float)mean * scl; }
    else       { g_c2s[c] = scl; g_c2b[c] = beta[c] - (float)mean * scl; }
}

// ---------------- fused BN1-apply + quant_act(alpha2) -> int8 NHWC padded ------------
__global__ void k_quant2(const float* __restrict__ a2p)
{
    int u = blockIdx.x*256 + threadIdx.x;           // over NPIX*16
    int p = u >> 4, cg = u & 15;
    float al = a2p[0], sc = al / 127.0f;
    float4 xv = *reinterpret_cast<const float4*>(&g_X1[p*64 + cg*4]);
    union { int8_t b[4]; uchar4 v; } r;
    const float* xf = (const float*)&xv;
    #pragma unroll
    for (int j = 0; j < 4; j++) {
        int c = cg*4 + j;
        float v = xf[j] * g_c1s[c] + g_c1b[c];
        v = fminf(fmaxf(v, -al), al);
        r.b[j] = (int8_t)(int)rintf(v / sc);
    }
    int n = p / HW, hw = p % HW, h = hw / WW, w = hw % WW;
    *reinterpret_cast<uchar4*>(&g_A2[((n*HP + h+1)*WP + (w+1))*64 + cg*4]) = r.v;
}

// ---------------- final: pure elementwise NCHW (Y2 fp16 NCHW) ------------------------
__global__ void k_final(const float* __restrict__ idn, const float* __restrict__ shortcut,
                        float* __restrict__ out, const float* __restrict__ bits,
                        const float* __restrict__ f, const float* __restrict__ bout,
                        int out_size)
{
    int c = blockIdx.y, n = blockIdx.z;
    int base4 = ((n*CC + c)*HW >> 2) + blockIdx.x*256 + threadIdx.x;  // float4 index
    float scl = g_c2s[c], sft = g_c2b[c], sh = shortcut[0];
    const __half2* Y2 = reinterpret_cast<const __half2*>(g_Y2h);
    float2 ya = __half22float2(Y2[base4*2]);
    float2 yb = __half22float2(Y2[base4*2 + 1]);
    float4 v = reinterpret_cast<const float4*>(idn)[base4];
    float4 r;
    r.x = v.x*sh + ya.x*scl + sft;
    r.y = v.y*sh + ya.y*scl + sft;
    r.z = v.z*sh + yb.x*scl + sft;
    r.w = v.w*sh + yb.y*scl + sft;
    reinterpret_cast<float4*>(out)[base4] = r;
    if (blockIdx.x == 0 && blockIdx.y == 0 && blockIdx.z == 0 && threadIdx.x == 0
        && out_size >= VOL + 3) {
        out[VOL]   = bits[0];
        out[VOL+1] = f[0];
        out[VOL+2] = bout[0];
    }
}

// ---------------- launch -------------------------------------------------------------
extern "C" void kernel_launch(void* const* d_in, const int* in_sizes, int n_in,
                              void* d_out, int out_size)
{
    (void)in_sizes; (void)n_in;
    const float* identity = (const float*)d_in[0];
    const float* bits     = (const float*)d_in[1];
    const float* f        = (const float*)d_in[2];
    const float* bits_out = (const float*)d_in[3];
    const float* w1       = (const float*)d_in[4];
    const float* w2       = (const float*)d_in[5];
    const float* alpha1   = (const float*)d_in[6];
    const float* alpha2   = (const float*)d_in[7];
    const float* gamma1   = (const float*)d_in[8];
    const float* beta1    = (const float*)d_in[9];
    const float* gamma2   = (const float*)d_in[10];
    const float* beta2    = (const float*)d_in[11];
    const float* prelu_a  = (const float*)d_in[12];
    const float* shortcut = (const float*)d_in[13];
    float* out = (float*)d_out;

    const int SMEM = (1584 + 2304) * 16;  // 62208 B dynamic shared for conv
    cudaFuncSetAttribute(k_conv<true>,  cudaFuncAttributeMaxDynamicSharedMemorySize, SMEM);
    cudaFuncSetAttribute(k_conv<false>, cudaFuncAttributeMaxDynamicSharedMemorySize, SMEM);

    k_wquant<<<3, 256>>>(w1, w2, alpha1, alpha2);
    k_quant1<<<dim3(6,192,8), dim3(32,8)>>>(identity, alpha1);
    k_conv<true><<<dim3(3,48,8), 512, SMEM>>>(prelu_a);
    k_stats<true><<<1, 64>>>(gamma1, beta1);
    k_quant2<<<(NPIX*16)/256, 256>>>(alpha2);
    k_conv<false><<<dim3(3,48,8), 512, SMEM>>>(prelu_a);
    k_stats<false><<<1, 64>>>(gamma2, beta2);
    k_final<<<dim3(HW/4/256, CC, NB), 256>>>(identity, shortcut, out, bits, f, bits_out, out_size);
}

// round 6
// speedup vs baseline: 1.1645x; 1.0139x over previous
#include <cuda_runtime.h>
#include <cuda_fp16.h>
#include <cstdint>

#define NB 8
#define CC 64
#define HH 192
#define WW 192
#define HP 194
#define WP 194
#define NPIX (NB*HH*WW)      /* 294912 */
#define VOL  (NPIX*CC)       /* 18874368 */
#define HW   (HH*WW)         /* 36864 */

// ---------------- scratch (static device globals; zero-initialized) ----------------
__device__ int8_t g_A1[NB*HP*WP*CC];     // quantized act 1, NHWC, zero-padded halo
__device__ float  g_X1[VOL];             // conv1 output post-prelu, NHWC fp32 (feeds round())
__device__ __half g_Y2h[VOL];            // conv2 raw output, NCHW fp16 (affine-only downstream)
__device__ int8_t g_w1p[9*64*64];        // packed weights [tap][cout][cin] bytes
__device__ int8_t g_w2p[9*64*64];
__device__ float  g_S[2];                // combined conv scales (a_scale * w_scale)
__device__ double g_bn1s[CC], g_bn1q[CC], g_bn2s[CC], g_bn2q[CC];
__device__ float  g_c1s[CC], g_c1b[CC], g_c2s[CC], g_c2b[CC];

// ---------------- kernel 0: zero BN accumulators (separate so conv1 = launch #4) -----
__global__ void k_zero()
{
    int t = threadIdx.x;
    if (t < CC) { g_bn1s[t] = 0.0; g_bn1q[t] = 0.0; g_bn2s[t] = 0.0; g_bn2q[t] = 0.0; }
}

// ---------------- kernel 1: weight quantization --------------------------------------
__global__ void k_wquant(const float* __restrict__ w1, const float* __restrict__ w2,
                         const float* __restrict__ a1, const float* __restrict__ a2)
{
    int b = blockIdx.x, t = threadIdx.x;
    const float* w = b ? w2 : w1;
    int8_t* wp = b ? g_w2p : g_w1p;
    __shared__ float red[256];
    float m = 0.f;
    for (int i = t; i < 36864; i += 256) m = fmaxf(m, fabsf(w[i]));
    red[t] = m; __syncthreads();
    for (int s = 128; s; s >>= 1) { if (t < s) red[t] = fmaxf(red[t], red[t+s]); __syncthreads(); }
    float sw = red[0] / 127.0f;   // weight scale
    if (t == 0) g_S[b] = ((b ? a2[0] : a1[0]) / 127.0f) * sw;
    for (int i = t; i < 36864; i += 256) {
        float q = rintf(w[i] / sw);
        q = fminf(fmaxf(q, -127.f), 127.f);
        int o = i / 576, ci = (i / 9) % 64, tap = i % 9;
        wp[(tap*64 + o)*64 + ci] = (int8_t)q;     // [tap][cout][cin]
    }
}

// ---------------- kernel 2: quantize identity, NCHW fp32 -> NHWC int8 (padded) -------
__global__ void k_quant1(const float* __restrict__ x, const float* __restrict__ a1p)
{
    __shared__ uchar4 sb[32][17];
    int w0 = blockIdx.x*32, h = blockIdx.y, n = blockIdx.z;
    int tx = threadIdx.x, ty = threadIdx.y;         // 32 x 8
    float al = a1p[0], sc = al / 127.0f;
    #pragma unroll
    for (int k = 0; k < 2; k++) {
        int cg = ty + 8*k;                           // 0..15
        union { int8_t b[4]; uchar4 v; } u;
        #pragma unroll
        for (int j = 0; j < 4; j++) {
            int c = cg*4 + j;
            float xv = x[((n*CC + c)*HH + h)*WW + w0 + tx];
            xv = fminf(fmaxf(xv, -al), al);
            u.b[j] = (int8_t)(int)rintf(xv / sc);
        }
        sb[tx][cg] = u.v;
    }
    __syncthreads();
    int tid = ty*32 + tx;
    #pragma unroll
    for (int k = 0; k < 2; k++) {
        int uu = tid + 256*k;                        // 0..511
        int p = uu >> 4, cg = uu & 15;
        *reinterpret_cast<uchar4*>(&g_A1[((n*HP + h+1)*WP + (w0+p+1))*64 + cg*4]) = sb[p][cg];
    }
}

// ---------------- conv engine: int8 tensor-core implicit GEMM (IMMA m16n8k32) --------
// Block: 512 threads = 16 warps. Tile: 256 pixels (4 rows x 64 wide) x 64 couts.
// FIRST: reads pre-quantized g_A1; writes X1 NHWC fp32, PReLU fused.
// !FIRST: reads X1 fp32 directly, fuses BN1-apply + quant_act(alpha2) into the
//         smem loader (no A2 intermediate); writes Y2 NCHW fp16 with shfl-packed
//         sector-complete half2 stores.
// Both: fused per-channel sum/sumsq (fp32) -> global double atomics.
template<bool FIRST>
__global__ void __launch_bounds__(512) k_conv(const float* __restrict__ pa_p,
                                              const float* __restrict__ a2p)
{
    extern __shared__ int4 smem[];
    int4* sA = smem;                 // 6 rows x 66 pix x 4 = 1584 int4
    int4* sW = smem + 1584;          // 2304 int4
    __shared__ float ss[64], sq[64];
    __shared__ float sc1[64], sb1[64];
    const uint32_t* sAw = (const uint32_t*)sA;
    const uint32_t* sWw = (const uint32_t*)sW;

    const int4* W4 = (const int4*)(FIRST ? g_w1p : g_w2p);
    double* bs     = FIRST ? g_bn1s : g_bn2s;
    double* bq     = FIRST ? g_bn1q : g_bn2q;

    int tid = threadIdx.x;
    int lane = tid & 31, warp = tid >> 5;
    int w0 = blockIdx.x*64, H0 = blockIdx.y*4, n = blockIdx.z;

    if (tid < 64) { ss[tid] = 0.f; sq[tid] = 0.f; }

    if (FIRST) {
        const int4* A4 = (const int4*)g_A1;
        for (int u = tid; u < 1584; u += 512) {
            int r = u / 264, rem = u % 264, pix = rem >> 2, c4 = rem & 3;
            sA[(r*66 + pix)*4 + (c4 ^ ((pix & 6) >> 1))] =
                A4[((n*HP + H0 + r)*WP + w0 + pix)*4 + c4];
        }
    } else {
        if (tid < 64) { sc1[tid] = g_c1s[tid]; sb1[tid] = g_c1b[tid]; }
        __syncthreads();
        float al = a2p[0], sc = al / 127.0f;
        for (int u = tid; u < 1584; u += 512) {
            int r = u / 264, rem = u % 264, pix = rem >> 2, c4 = rem & 3;
            int hr = H0 + r - 1, wc = w0 + pix - 1;
            union { int8_t b[16]; int4 v; } pk;
            pk.v = make_int4(0, 0, 0, 0);
            if (hr >= 0 && hr < HH && wc >= 0 && wc < WW) {
                const float4* src = reinterpret_cast<const float4*>(
                    &g_X1[(size_t)((n*HW + hr*WW + wc)*64 + c4*16)]);
                #pragma unroll
                for (int q2 = 0; q2 < 4; q2++) {
                    float4 v = src[q2];
                    int cb = c4*16 + q2*4;
                    float vv[4] = {v.x, v.y, v.z, v.w};
                    #pragma unroll
                    for (int j = 0; j < 4; j++) {
                        float t = vv[j]*sc1[cb+j] + sb1[cb+j];
                        t = fminf(fmaxf(t, -al), al);
                        pk.b[q2*4 + j] = (int8_t)(int)rintf(t / sc);
                    }
                }
            }
            sA[(r*66 + pix)*4 + (c4 ^ ((pix & 6) >> 1))] = pk.v;
        }
    }
    for (int u = tid; u < 2304; u += 512) {
        int c4 = u & 3, co = (u >> 2) & 63, t = u >> 8;
        sW[(t*64 + co)*4 + (c4 ^ ((co & 6) >> 1))] = W4[u];
    }
    __syncthreads();

    int g = lane >> 2, t4 = lane & 3;
    int pg = warp >> 1, ch = warp & 1;
    int lrow = pg >> 1, colb = (pg & 1) * 32;

    int acc[2][4][4];
    #pragma unroll
    for (int mg = 0; mg < 2; mg++)
        #pragma unroll
        for (int o = 0; o < 4; o++)
            #pragma unroll
            for (int j = 0; j < 4; j++) acc[mg][o][j] = 0;

    #pragma unroll 1
    for (int t = 0; t < 9; t++) {
        int dh = t / 3, dw = t % 3;
        int rs = lrow + dh;
        uint32_t af[2][2][4];
        #pragma unroll
        for (int c = 0; c < 2; c++) {
            int cin = 32*c + 4*t4;
            #pragma unroll
            for (int mg = 0; mg < 2; mg++) {
                int p0 = colb + mg*16 + g + dw;
                int off = (rs*66 + p0)*16 + ((cin ^ ((p0 & 6) << 3)) >> 2);
                af[c][mg][0] = sAw[off];
                af[c][mg][1] = sAw[off + 128];       // p0+8 keeps (p&6) bits
                af[c][mg][2] = sAw[off ^ 4];
                af[c][mg][3] = sAw[(off + 128) ^ 4];
            }
        }
        #pragma unroll
        for (int o = 0; o < 4; o++) {
            int co = ch*32 + o*8 + g;
            #pragma unroll
            for (int c = 0; c < 2; c++) {
                int cin = 32*c + 4*t4;
                int boff = (t*64 + co)*16 + ((cin ^ ((co & 6) << 3)) >> 2);
                uint32_t b0 = sWw[boff];
                uint32_t b1 = sWw[boff ^ 4];
                #pragma unroll
                for (int mg = 0; mg < 2; mg++) {
                    asm volatile(
                        "mma.sync.aligned.m16n8k32.row.col.s32.s8.s8.s32 "
                        "{%0,%1,%2,%3},{%4,%5,%6,%7},{%8,%9},{%0,%1,%2,%3};"
                        : "+r"(acc[mg][o][0]), "+r"(acc[mg][o][1]),
                          "+r"(acc[mg][o][2]), "+r"(acc[mg][o][3])
                        : "r"(af[c][mg][0]), "r"(af[c][mg][1]),
                          "r"(af[c][mg][2]), "r"(af[c][mg][3]),
                          "r"(b0), "r"(b1));
                }
            }
        }
    }

    float S  = g_S[FIRST ? 0 : 1];
    float pa = FIRST ? pa_p[0] : 0.f;
    float sj[4][2], qj[4][2];
    #pragma unroll
    for (int o = 0; o < 4; o++) { sj[o][0]=sj[o][1]=qj[o][0]=qj[o][1]=0.f; }

    bool geven = (g & 1) == 0;
    #pragma unroll
    for (int mg = 0; mg < 2; mg++) {
        int pixl = (H0 + lrow)*WW + w0 + colb + mg*16;   // pixel index within image
        #pragma unroll
        for (int o = 0; o < 4; o++) {
            int col = ch*32 + o*8 + 2*t4;
            float y0 = S * (float)acc[mg][o][0];
            float y1 = S * (float)acc[mg][o][1];
            float y2 = S * (float)acc[mg][o][2];
            float y3 = S * (float)acc[mg][o][3];
            if (FIRST) {
                y0 = (y0 >= 0.f) ? y0 : pa*y0;
                y1 = (y1 >= 0.f) ? y1 : pa*y1;
                y2 = (y2 >= 0.f) ? y2 : pa*y2;
                y3 = (y3 >= 0.f) ? y3 : pa*y3;
                int row0 = n*HW + pixl + g, row1 = row0 + 8;
                *reinterpret_cast<float2*>(&g_X1[row0*64 + col]) = make_float2(y0, y1);
                *reinterpret_cast<float2*>(&g_X1[row1*64 + col]) = make_float2(y2, y3);
            } else {
                // shfl-pack neighbor-g pixels into half2; sector-complete stores
                float y0n = __shfl_xor_sync(0xffffffffu, y0, 4);
                float y1n = __shfl_xor_sync(0xffffffffu, y1, 4);
                float y2n = __shfl_xor_sync(0xffffffffu, y2, 4);
                float y3n = __shfl_xor_sync(0xffffffffu, y3, 4);
                int b0 = (n*64 + col)*HW + pixl;     // channel col
                int b1 = b0 + HW;                    // channel col+1
                int addrA = geven ? (b0 + g)     : (b1 + g - 1);
                int addrB = geven ? (b0 + 8 + g) : (b1 + 7 + g);
                __half2 vA = geven ? __floats2half2_rn(y0, y0n) : __floats2half2_rn(y1n, y1);
                __half2 vB = geven ? __floats2half2_rn(y2, y2n) : __floats2half2_rn(y3n, y3);
                *reinterpret_cast<__half2*>(&g_Y2h[addrA]) = vA;
                *reinterpret_cast<__half2*>(&g_Y2h[addrB]) = vB;
            }
            sj[o][0] += y0 + y2;  qj[o][0] += y0*y0 + y2*y2;
            sj[o][1] += y1 + y3;  qj[o][1] += y1*y1 + y3*y3;
        }
    }
    // reduce over g (lane bits 2..4), then smem atomics from g==0 lanes
    #pragma unroll
    for (int o = 0; o < 4; o++) {
        #pragma unroll
        for (int j = 0; j < 2; j++) {
            float s = sj[o][j], q = qj[o][j];
            #pragma unroll
            for (int off = 4; off < 32; off <<= 1) {
                s += __shfl_xor_sync(0xffffffffu, s, off);
                q += __shfl_xor_sync(0xffffffffu, q, off);
            }
            if (g == 0) {
                int chan = ch*32 + o*8 + t4*2 + j;
                atomicAdd(&ss[chan], s);
                atomicAdd(&sq[chan], q);
            }
        }
    }
    __syncthreads();
    if (tid < 64) {
        atomicAdd(&bs[tid], (double)ss[tid]);
        atomicAdd(&bq[tid], (double)sq[tid]);
    }
}

// ---------------- BN stats finalize -> per-channel scale/shift ----------------------
template<bool FIRST>
__global__ void k_stats(const float* __restrict__ gamma, const float* __restrict__ beta)
{
    int c = threadIdx.x;
    const double* bs = FIRST ? g_bn1s : g_bn2s;
    const double* bq = FIRST ? g_bn1q : g_bn2q;
    double invn = 1.0 / (double)NPIX;
    double mean = bs[c] * invn;
    double var  = bq[c] * invn - mean*mean;
    float scl = gamma[c] * rsqrtf((float)var + 1e-5f);
    if (FIRST) { g_c1s[c] = scl; g_c1b[c] = beta[c] - (float)mean * scl; }
    else       { g_c2s[c] = scl; g_c2b[c] = beta[c] - (float)mean * scl; }
}

// ---------------- final: pure elementwise NCHW (Y2 fp16 NCHW) ------------------------
__global__ void k_final(const float* __restrict__ idn, const float* __restrict__ shortcut,
                        float* __restrict__ out, const float* __restrict__ bits,
                        const float* __restrict__ f, const float* __restrict__ bout,
                        int out_size)
{
    int c = blockIdx.y, n = blockIdx.z;
    int base4 = ((n*CC + c)*HW >> 2) + blockIdx.x*256 + threadIdx.x;  // float4 index
    float scl = g_c2s[c], sft = g_c2b[c], sh = shortcut[0];
    const __half2* Y2 = reinterpret_cast<const __half2*>(g_Y2h);
    float2 ya = __half22float2(Y2[base4*2]);
    float2 yb = __half22float2(Y2[base4*2 + 1]);
    float4 v = reinterpret_cast<const float4*>(idn)[base4];
    float4 r;
    r.x = v.x*sh + ya.x*scl + sft;
    r.y = v.y*sh + ya.y*scl + sft;
    r.z = v.z*sh + yb.x*scl + sft;
    r.w = v.w*sh + yb.y*scl + sft;
    reinterpret_cast<float4*>(out)[base4] = r;
    if (blockIdx.x == 0 && blockIdx.y == 0 && blockIdx.z == 0 && threadIdx.x == 0
        && out_size >= VOL + 3) {
        out[VOL]   = bits[0];
        out[VOL+1] = f[0];
        out[VOL+2] = bout[0];
    }
}

// ---------------- launch -------------------------------------------------------------
extern "C" void kernel_launch(void* const* d_in, const int* in_sizes, int n_in,
                              void* d_out, int out_size)
{
    (void)in_sizes; (void)n_in;
    const float* identity = (const float*)d_in[0];
    const float* bits     = (const float*)d_in[1];
    const float* f        = (const float*)d_in[2];
    const float* bits_out = (const float*)d_in[3];
    const float* w1       = (const float*)d_in[4];
    const float* w2       = (const float*)d_in[5];
    const float* alpha1   = (const float*)d_in[6];
    const float* alpha2   = (const float*)d_in[7];
    const float* gamma1   = (const float*)d_in[8];
    const float* beta1    = (const float*)d_in[9];
    const float* gamma2   = (const float*)d_in[10];
    const float* beta2    = (const float*)d_in[11];
    const float* prelu_a  = (const float*)d_in[12];
    const float* shortcut = (const float*)d_in[13];
    float* out = (float*)d_out;

    const int SMEM = (1584 + 2304) * 16;  // 62208 B dynamic shared for conv
    cudaFuncSetAttribute(k_conv<true>,  cudaFuncAttributeMaxDynamicSharedMemorySize, SMEM);
    cudaFuncSetAttribute(k_conv<false>, cudaFuncAttributeMaxDynamicSharedMemorySize, SMEM);

    k_zero<<<1, 64>>>();
    k_wquant<<<2, 256>>>(w1, w2, alpha1, alpha2);
    k_quant1<<<dim3(6,192,8), dim3(32,8)>>>(identity, alpha1);
    k_conv<true><<<dim3(3,48,8), 512, SMEM>>>(prelu_a, alpha2);      // ncu captures this
    k_stats<true><<<1, 64>>>(gamma1, beta1);
    k_conv<false><<<dim3(3,48,8), 512, SMEM>>>(prelu_a, alpha2);
    k_stats<false><<<1, 64>>>(gamma2, beta2);
    k_final<<<dim3(HW/4/256, CC, NB), 256>>>(identity, shortcut, out, bits, f, bits_out, out_size);
}

// round 8
// speedup vs baseline: 1.1685x; 1.0035x over previous
#include <cuda_runtime.h>
#include <cuda_fp16.h>
#include <cstdint>

#define NB 8
#define CC 64
#define HH 192
#define WW 192
#define HP 194
#define WP 194
#define NPIX (NB*HH*WW)      /* 294912 */
#define VOL  (NPIX*CC)       /* 18874368 */
#define HW   (HH*WW)         /* 36864 */

// ---------------- scratch (static device globals; zero-initialized) ----------------
__device__ int8_t g_A1[NB*HP*WP*CC];     // quantized act 1, NHWC, zero-padded halo
__device__ float  g_X1[VOL];             // conv1 output post-prelu, NHWC fp32 (feeds round())
__device__ __half g_Y2h[VOL];            // conv2 raw output, NCHW fp16 (affine-only downstream)
__device__ int8_t g_w1p[9*64*64];        // packed weights [tap][cout][cin] bytes
__device__ int8_t g_w2p[9*64*64];
__device__ float  g_S[2];                // combined conv scales (a_scale * w_scale)
__device__ double g_bn1s[CC], g_bn1q[CC], g_bn2s[CC], g_bn2q[CC];
__device__ float  g_c1s[CC], g_c1b[CC], g_c2s[CC], g_c2b[CC];

// ---------------- kernel 0: zero BN accumulators (separate so conv1 = launch #4) -----
__global__ void k_zero()
{
    int t = threadIdx.x;
    if (t < CC) { g_bn1s[t] = 0.0; g_bn1q[t] = 0.0; g_bn2s[t] = 0.0; g_bn2q[t] = 0.0; }
}

// ---------------- kernel 1: weight quantization --------------------------------------
__global__ void k_wquant(const float* __restrict__ w1, const float* __restrict__ w2,
                         const float* __restrict__ a1, const float* __restrict__ a2)
{
    int b = blockIdx.x, t = threadIdx.x;
    const float* w = b ? w2 : w1;
    int8_t* wp = b ? g_w2p : g_w1p;
    __shared__ float red[256];
    float m = 0.f;
    for (int i = t; i < 36864; i += 256) m = fmaxf(m, fabsf(w[i]));
    red[t] = m; __syncthreads();
    for (int s = 128; s; s >>= 1) { if (t < s) red[t] = fmaxf(red[t], red[t+s]); __syncthreads(); }
    float sw = red[0] / 127.0f;   // weight scale
    if (t == 0) g_S[b] = ((b ? a2[0] : a1[0]) / 127.0f) * sw;
    for (int i = t; i < 36864; i += 256) {
        float q = rintf(w[i] / sw);
        q = fminf(fmaxf(q, -127.f), 127.f);
        int o = i / 576, ci = (i / 9) % 64, tap = i % 9;
        wp[(tap*64 + o)*64 + ci] = (int8_t)q;     // [tap][cout][cin]
    }
}

// ---------------- kernel 2: quantize identity, NCHW fp32 -> NHWC int8 (padded) -------
__global__ void k_quant1(const float* __restrict__ x, const float* __restrict__ a1p)
{
    __shared__ uchar4 sb[32][17];
    int w0 = blockIdx.x*32, h = blockIdx.y, n = blockIdx.z;
    int tx = threadIdx.x, ty = threadIdx.y;         // 32 x 8
    float al = a1p[0], sc = al / 127.0f;
    #pragma unroll
    for (int k = 0; k < 2; k++) {
        int cg = ty + 8*k;                           // 0..15
        union { int8_t b[4]; uchar4 v; } u;
        #pragma unroll
        for (int j = 0; j < 4; j++) {
            int c = cg*4 + j;
            float xv = x[((n*CC + c)*HH + h)*WW + w0 + tx];
            xv = fminf(fmaxf(xv, -al), al);
            u.b[j] = (int8_t)(int)rintf(xv / sc);
        }
        sb[tx][cg] = u.v;
    }
    __syncthreads();
    int tid = ty*32 + tx;
    #pragma unroll
    for (int k = 0; k < 2; k++) {
        int uu = tid + 256*k;                        // 0..511
        int p = uu >> 4, cg = uu & 15;
        *reinterpret_cast<uchar4*>(&g_A1[((n*HP + h+1)*WP + (w0+p+1))*64 + cg*4]) = sb[p][cg];
    }
}

// ---------------- conv engine: int8 tensor-core implicit GEMM (IMMA m16n8k32) --------
// Block: 512 threads = 16 warps. Tile: 256 pixels (4 rows x 64 wide) x 64 couts.
// FIRST: reads pre-quantized g_A1; writes X1 NHWC fp32, PReLU fused.
// !FIRST: reads X1 fp32 directly, fuses BN1-apply + quant_act(alpha2) into the
//         smem loader (no A2 intermediate); writes Y2 NCHW fp16 with shfl-packed
//         sector-complete half2 stores.
// Both: fused per-channel sum/sumsq (fp32) -> global double atomics.
template<bool FIRST>
__global__ void __launch_bounds__(512) k_conv(const float* __restrict__ pa_p,
                                              const float* __restrict__ a2p)
{
    extern __shared__ int4 smem[];
    int4* sA = smem;                 // 6 rows x 66 pix x 4 = 1584 int4
    int4* sW = smem + 1584;          // 2304 int4
    __shared__ float ss[64], sq[64];
    __shared__ float sc1[64], sb1[64];
    const uint32_t* sAw = (const uint32_t*)sA;
    const uint32_t* sWw = (const uint32_t*)sW;

    const int4* W4 = (const int4*)(FIRST ? g_w1p : g_w2p);
    double* bs     = FIRST ? g_bn1s : g_bn2s;
    double* bq     = FIRST ? g_bn1q : g_bn2q;

    int tid = threadIdx.x;
    int lane = tid & 31, warp = tid >> 5;
    int w0 = blockIdx.x*64, H0 = blockIdx.y*4, n = blockIdx.z;

    if (tid < 64) { ss[tid] = 0.f; sq[tid] = 0.f; }

    if (FIRST) {
        const int4* A4 = (const int4*)g_A1;
        for (int u = tid; u < 1584; u += 512) {
            int r = u / 264, rem = u % 264, pix = rem >> 2, c4 = rem & 3;
            sA[(r*66 + pix)*4 + (c4 ^ ((pix & 6) >> 1))] =
                A4[((n*HP + H0 + r)*WP + w0 + pix)*4 + c4];
        }
    } else {
        if (tid < 64) { sc1[tid] = g_c1s[tid]; sb1[tid] = g_c1b[tid]; }
        __syncthreads();
        float al = a2p[0], sc = al / 127.0f;
        for (int u = tid; u < 1584; u += 512) {
            int r = u / 264, rem = u % 264, pix = rem >> 2, c4 = rem & 3;
            int hr = H0 + r - 1, wc = w0 + pix - 1;
            union { int8_t b[16]; int4 v; } pk;
            pk.v = make_int4(0, 0, 0, 0);
            if (hr >= 0 && hr < HH && wc >= 0 && wc < WW) {
                const float4* src = reinterpret_cast<const float4*>(
                    &g_X1[(size_t)((n*HW + hr*WW + wc)*64 + c4*16)]);
                #pragma unroll
                for (int q2 = 0; q2 < 4; q2++) {
                    float4 v = src[q2];
                    int cb = c4*16 + q2*4;
                    float vv[4] = {v.x, v.y, v.z, v.w};
                    #pragma unroll
                    for (int j = 0; j < 4; j++) {
                        float t = vv[j]*sc1[cb+j] + sb1[cb+j];
                        t = fminf(fmaxf(t, -al), al);
                        pk.b[q2*4 + j] = (int8_t)(int)rintf(t / sc);
                    }
                }
            }
            sA[(r*66 + pix)*4 + (c4 ^ ((pix & 6) >> 1))] = pk.v;
        }
    }
    for (int u = tid; u < 2304; u += 512) {
        int c4 = u & 3, co = (u >> 2) & 63, t = u >> 8;
        sW[(t*64 + co)*4 + (c4 ^ ((co & 6) >> 1))] = W4[u];
    }
    __syncthreads();

    int g = lane >> 2, t4 = lane & 3;
    int pg = warp >> 1, ch = warp & 1;
    int lrow = pg >> 1, colb = (pg & 1) * 32;

    int acc[2][4][4];
    #pragma unroll
    for (int mg = 0; mg < 2; mg++)
        #pragma unroll
        for (int o = 0; o < 4; o++)
            #pragma unroll
            for (int j = 0; j < 4; j++) acc[mg][o][j] = 0;

    #pragma unroll 1
    for (int t = 0; t < 9; t++) {
        int dh = t / 3, dw = t % 3;
        int rs = lrow + dh;
        uint32_t af[2][2][4];
        #pragma unroll
        for (int c = 0; c < 2; c++) {
            int cin = 32*c + 4*t4;
            #pragma unroll
            for (int mg = 0; mg < 2; mg++) {
                int p0 = colb + mg*16 + g + dw;
                int off = (rs*66 + p0)*16 + ((cin ^ ((p0 & 6) << 3)) >> 2);
                af[c][mg][0] = sAw[off];
                af[c][mg][1] = sAw[off + 128];       // p0+8 keeps (p&6) bits
                af[c][mg][2] = sAw[off ^ 4];
                af[c][mg][3] = sAw[(off + 128) ^ 4];
            }
        }
        #pragma unroll
        for (int o = 0; o < 4; o++) {
            int co = ch*32 + o*8 + g;
            #pragma unroll
            for (int c = 0; c < 2; c++) {
                int cin = 32*c + 4*t4;
                int boff = (t*64 + co)*16 + ((cin ^ ((co & 6) << 3)) >> 2);
                uint32_t b0 = sWw[boff];
                uint32_t b1 = sWw[boff ^ 4];
                #pragma unroll
                for (int mg = 0; mg < 2; mg++) {
                    asm volatile(
                        "mma.sync.aligned.m16n8k32.row.col.s32.s8.s8.s32 "
                        "{%0,%1,%2,%3},{%4,%5,%6,%7},{%8,%9},{%0,%1,%2,%3};"
                        : "+r"(acc[mg][o][0]), "+r"(acc[mg][o][1]),
                          "+r"(acc[mg][o][2]), "+r"(acc[mg][o][3])
                        : "r"(af[c][mg][0]), "r"(af[c][mg][1]),
                          "r"(af[c][mg][2]), "r"(af[c][mg][3]),
                          "r"(b0), "r"(b1));
                }
            }
        }
    }

    float S  = g_S[FIRST ? 0 : 1];
    float pa = FIRST ? pa_p[0] : 0.f;
    float sj[4][2], qj[4][2];
    #pragma unroll
    for (int o = 0; o < 4; o++) { sj[o][0]=sj[o][1]=qj[o][0]=qj[o][1]=0.f; }

    bool geven = (g & 1) == 0;
    #pragma unroll
    for (int mg = 0; mg < 2; mg++) {
        int pixl = (H0 + lrow)*WW + w0 + colb + mg*16;   // pixel index within image
        #pragma unroll
        for (int o = 0; o < 4; o++) {
            int col = ch*32 + o*8 + 2*t4;
            float y0 = S * (float)acc[mg][o][0];
            float y1 = S * (float)acc[mg][o][1];
            float y2 = S * (float)acc[mg][o][2];
            float y3 = S * (float)acc[mg][o][3];
            if (FIRST) {
                y0 = (y0 >= 0.f) ? y0 : pa*y0;
                y1 = (y1 >= 0.f) ? y1 : pa*y1;
                y2 = (y2 >= 0.f) ? y2 : pa*y2;
                y3 = (y3 >= 0.f) ? y3 : pa*y3;
                int row0 = n*HW + pixl + g, row1 = row0 + 8;
                *reinterpret_cast<float2*>(&g_X1[row0*64 + col]) = make_float2(y0, y1);
                *reinterpret_cast<float2*>(&g_X1[row1*64 + col]) = make_float2(y2, y3);
            } else {
                // shfl-pack neighbor-g pixels into half2; sector-complete stores
                float y0n = __shfl_xor_sync(0xffffffffu, y0, 4);
                float y1n = __shfl_xor_sync(0xffffffffu, y1, 4);
                float y2n = __shfl_xor_sync(0xffffffffu, y2, 4);
                float y3n = __shfl_xor_sync(0xffffffffu, y3, 4);
                int b0 = (n*64 + col)*HW + pixl;     // channel col
                int b1 = b0 + HW;                    // channel col+1
                int addrA = geven ? (b0 + g)     : (b1 + g - 1);
                int addrB = geven ? (b0 + 8 + g) : (b1 + 7 + g);
                __half2 vA = geven ? __floats2half2_rn(y0, y0n) : __floats2half2_rn(y1n, y1);
                __half2 vB = geven ? __floats2half2_rn(y2, y2n) : __floats2half2_rn(y3n, y3);
                *reinterpret_cast<__half2*>(&g_Y2h[addrA]) = vA;
                *reinterpret_cast<__half2*>(&g_Y2h[addrB]) = vB;
            }
            sj[o][0] += y0 + y2;  qj[o][0] += y0*y0 + y2*y2;
            sj[o][1] += y1 + y3;  qj[o][1] += y1*y1 + y3*y3;
        }
    }
    // reduce over g (lane bits 2..4), then smem atomics from g==0 lanes
    #pragma unroll
    for (int o = 0; o < 4; o++) {
        #pragma unroll
        for (int j = 0; j < 2; j++) {
            float s = sj[o][j], q = qj[o][j];
            #pragma unroll
            for (int off = 4; off < 32; off <<= 1) {
                s += __shfl_xor_sync(0xffffffffu, s, off);
                q += __shfl_xor_sync(0xffffffffu, q, off);
            }
            if (g == 0) {
                int chan = ch*32 + o*8 + t4*2 + j;
                atomicAdd(&ss[chan], s);
                atomicAdd(&sq[chan], q);
            }
        }
    }
    __syncthreads();
    if (tid < 64) {
        atomicAdd(&bs[tid], (double)ss[tid]);
        atomicAdd(&bq[tid], (double)sq[tid]);
    }
}

// ---------------- BN stats finalize -> per-channel scale/shift ----------------------
template<bool FIRST>
__global__ void k_stats(const float* __restrict__ gamma, const float* __restrict__ beta)
{
    int c = threadIdx.x;
    const double* bs = FIRST ? g_bn1s : g_bn2s;
    const double* bq = FIRST ? g_bn1q : g_bn2q;
    double invn = 1.0 / (double)NPIX;
    double mean = bs[c] * invn;
    double var  = bq[c] * invn - mean*mean;
    float scl = gamma[c] * rsqrtf((float)var + 1e-5f);
    if (FIRST) { g_c1s[c] = scl; g_c1b[c] = beta[c] - (float)mean * scl; }
    else       { g_c2s[c] = scl; g_c2b[c] = beta[c] - (float)mean * scl; }
}

// ---------------- final: pure elementwise NCHW (Y2 fp16 NCHW) ------------------------
__global__ void k_final(const float* __restrict__ idn, const float* __restrict__ shortcut,
                        float* __restrict__ out, const float* __restrict__ bits,
                        const float* __restrict__ f, const float* __restrict__ bout,
                        int out_size)
{
    int c = blockIdx.y, n = blockIdx.z;
    int base4 = ((n*CC + c)*HW >> 2) + blockIdx.x*256 + threadIdx.x;  // float4 index
    float scl = g_c2s[c], sft = g_c2b[c], sh = shortcut[0];
    const __half2* Y2 = reinterpret_cast<const __half2*>(g_Y2h);
    float2 ya = __half22float2(Y2[base4*2]);
    float2 yb = __half22float2(Y2[base4*2 + 1]);
    float4 v = reinterpret_cast<const float4*>(idn)[base4];
    float4 r;
    r.x = v.x*sh + ya.x*scl + sft;
    r.y = v.y*sh + ya.y*scl + sft;
    r.z = v.z*sh + yb.x*scl + sft;
    r.w = v.w*sh + yb.y*scl + sft;
    reinterpret_cast<float4*>(out)[base4] = r;
    if (blockIdx.x == 0 && blockIdx.y == 0 && blockIdx.z == 0 && threadIdx.x == 0
        && out_size >= VOL + 3) {
        out[VOL]   = bits[0];
        out[VOL+1] = f[0];
        out[VOL+2] = bout[0];
    }
}

// ---------------- launch -------------------------------------------------------------
extern "C" void kernel_launch(void* const* d_in, const int* in_sizes, int n_in,
                              void* d_out, int out_size)
{
    (void)in_sizes; (void)n_in;
    const float* identity = (const float*)d_in[0];
    const float* bits     = (const float*)d_in[1];
    const float* f        = (const float*)d_in[2];
    const float* bits_out = (const float*)d_in[3];
    const float* w1       = (const float*)d_in[4];
    const float* w2       = (const float*)d_in[5];
    const float* alpha1   = (const float*)d_in[6];
    const float* alpha2   = (const float*)d_in[7];
    const float* gamma1   = (const float*)d_in[8];
    const float* beta1    = (const float*)d_in[9];
    const float* gamma2   = (const float*)d_in[10];
    const float* beta2    = (const float*)d_in[11];
    const float* prelu_a  = (const float*)d_in[12];
    const float* shortcut = (const float*)d_in[13];
    float* out = (float*)d_out;

    const int SMEM = (1584 + 2304) * 16;  // 62208 B dynamic shared for conv
    cudaFuncSetAttribute(k_conv<true>,  cudaFuncAttributeMaxDynamicSharedMemorySize, SMEM);
    cudaFuncSetAttribute(k_conv<false>, cudaFuncAttributeMaxDynamicSharedMemorySize, SMEM);

    k_zero<<<1, 64>>>();
    k_wquant<<<2, 256>>>(w1, w2, alpha1, alpha2);
    k_quant1<<<dim3(6,192,8), dim3(32,8)>>>(identity, alpha1);
    k_conv<true><<<dim3(3,48,8), 512, SMEM>>>(prelu_a, alpha2);      // ncu captures this
    k_stats<true><<<1, 64>>>(gamma1, beta1);
    k_conv<false><<<dim3(3,48,8), 512, SMEM>>>(prelu_a, alpha2);
    k_stats<false><<<1, 64>>>(gamma2, beta2);
    k_final<<<dim3(HW/4/256, CC, NB), 256>>>(identity, shortcut, out, bits, f, bits_out, out_size);
}